// round 11
// baseline (speedup 1.0000x reference)
#include <cuda_runtime.h>
#include <cuda_bf16.h>
#include <cuda_fp16.h>
#include <cstdint>

// Problem constants
#define B_   64
#define E_   4
#define N_   512
#define DIN_ 64
#define D0_  64
#define D1_  32

// Scratch (static __device__ arrays — allocation-free per harness rules)
__device__ __align__(256) __half g_A  [(size_t)B_ * N_ * N_];   // 32 MB fp16 A
__device__ __align__(256) float  g_h0 [(size_t)B_ * N_ * D0_];  // 8 MB (fp32 residual)
__device__ __align__(256) __half g_h0h[(size_t)B_ * N_ * D0_];  // 4 MB (fp16 operand)
__device__ __align__(256) float  g_o0 [(size_t)B_ * N_ * D1_];  // 4 MB (fp32 residual)
__device__ __align__(256) __half g_o0h[(size_t)B_ * N_ * D1_];  // 2 MB (fp16 operand)
__device__ int g_cnt[512];  // per-strip producer counters: raised to 8 by adjA, reset to 0 by consumer
__device__ int g_bar[B_];   // per-batch monotonic ticket counters (never reset; replay-safe)

// ---------------------------------------------------------------- helpers
__device__ __forceinline__ unsigned smem_u32(const void* p) {
    return (unsigned)__cvta_generic_to_shared(p);
}
__device__ __forceinline__ void cp_async16(unsigned s, const void* g) {
    asm volatile("cp.async.cg.shared.global [%0], [%1], 16;\n" :: "r"(s), "l"(g));
}
__device__ __forceinline__ void cp_commit() {
    asm volatile("cp.async.commit_group;\n");
}
template <int NWAIT>
__device__ __forceinline__ void cp_wait() {
    asm volatile("cp.async.wait_group %0;\n" :: "n"(NWAIT));
}
__device__ __forceinline__ void ldsm_x4(unsigned addr, unsigned& r0, unsigned& r1,
                                        unsigned& r2, unsigned& r3) {
    asm volatile("ldmatrix.sync.aligned.m8n8.x4.shared.b16 {%0,%1,%2,%3}, [%4];\n"
                 : "=r"(r0), "=r"(r1), "=r"(r2), "=r"(r3) : "r"(addr));
}
__device__ __forceinline__ void ldsm_x4_t(unsigned addr, unsigned& r0, unsigned& r1,
                                          unsigned& r2, unsigned& r3) {
    asm volatile("ldmatrix.sync.aligned.m8n8.x4.trans.shared.b16 {%0,%1,%2,%3}, [%4];\n"
                 : "=r"(r0), "=r"(r1), "=r"(r2), "=r"(r3) : "r"(addr));
}
__device__ __forceinline__ void mma_f16(float c[4], const unsigned a[4],
                                        unsigned b0, unsigned b1) {
    asm volatile(
        "mma.sync.aligned.m16n8k16.row.col.f32.f16.f16.f32 "
        "{%0,%1,%2,%3},{%4,%5,%6,%7},{%8,%9},{%0,%1,%2,%3};\n"
        : "+f"(c[0]), "+f"(c[1]), "+f"(c[2]), "+f"(c[3])
        : "r"(a[0]), "r"(a[1]), "r"(a[2]), "r"(a[3]), "r"(b0), "r"(b1));
}
__device__ __forceinline__ void mma_bf16(float c[4], const unsigned a[4],
                                         unsigned b0, unsigned b1) {
    asm volatile(
        "mma.sync.aligned.m16n8k16.row.col.f32.bf16.bf16.f32 "
        "{%0,%1,%2,%3},{%4,%5,%6,%7},{%8,%9},{%0,%1,%2,%3};\n"
        : "+f"(c[0]), "+f"(c[1]), "+f"(c[2]), "+f"(c[3])
        : "r"(a[0]), "r"(a[1]), "r"(a[2]), "r"(a[3]), "r"(b0), "r"(b1));
}
__device__ __forceinline__ void split_bf16(float a, __nv_bfloat16& hi, __nv_bfloat16& lo) {
    hi = __float2bfloat16(a);
    lo = __float2bfloat16(a - __bfloat162float(hi));
}

// ---------------------------------------------------------------- kernel 1: h0 = x @ W1 + b1  (tensor-core, split-bf16 internally)
#define H_XH   0
#define H_XL   18432
#define H_WH   36864
#define H_WL   46080
#define H_B1   55296
#define H_SMEM 55552

__global__ void __launch_bounds__(256) k_h0mma(const float* __restrict__ x,
                                               const float* __restrict__ W1,
                                               const float* __restrict__ b1) {
    extern __shared__ char sm[];
    __nv_bfloat16* xh = (__nv_bfloat16*)(sm + H_XH);   // [128][72]
    __nv_bfloat16* xl = (__nv_bfloat16*)(sm + H_XL);
    __nv_bfloat16* wh = (__nv_bfloat16*)(sm + H_WH);   // [64][72]
    __nv_bfloat16* wl = (__nv_bfloat16*)(sm + H_WL);
    float*        b1s = (float*)(sm + H_B1);

    int t = threadIdx.x, lane = t & 31, wid = t >> 5;
    int rt = blockIdx.x;
    const float* xg = x + (long)rt * 128 * 64;

#pragma unroll
    for (int i = 0; i < 8; i++) {
        int idx = t + i * 256;
        int r = idx >> 4, c = (idx & 15) * 4;
        float4 v = *(const float4*)(xg + r * 64 + c);
        __nv_bfloat162 h01, h23, l01, l23;
        split_bf16(v.x, h01.x, l01.x); split_bf16(v.y, h01.y, l01.y);
        split_bf16(v.z, h23.x, l23.x); split_bf16(v.w, h23.y, l23.y);
        uint2 uh, ul;
        uh.x = *reinterpret_cast<unsigned*>(&h01); uh.y = *reinterpret_cast<unsigned*>(&h23);
        ul.x = *reinterpret_cast<unsigned*>(&l01); ul.y = *reinterpret_cast<unsigned*>(&l23);
        *reinterpret_cast<uint2*>(xh + r * 72 + c) = uh;
        *reinterpret_cast<uint2*>(xl + r * 72 + c) = ul;
    }
#pragma unroll
    for (int i = 0; i < 4; i++) {
        int idx = t + i * 256;
        int r = idx >> 4, c = (idx & 15) * 4;
        float4 v = *(const float4*)(W1 + r * 64 + c);
        __nv_bfloat162 h01, h23, l01, l23;
        split_bf16(v.x, h01.x, l01.x); split_bf16(v.y, h01.y, l01.y);
        split_bf16(v.z, h23.x, l23.x); split_bf16(v.w, h23.y, l23.y);
        uint2 uh, ul;
        uh.x = *reinterpret_cast<unsigned*>(&h01); uh.y = *reinterpret_cast<unsigned*>(&h23);
        ul.x = *reinterpret_cast<unsigned*>(&l01); ul.y = *reinterpret_cast<unsigned*>(&l23);
        *reinterpret_cast<uint2*>(wh + r * 72 + c) = uh;
        *reinterpret_cast<uint2*>(wl + r * 72 + c) = ul;
    }
    if (t < 64) b1s[t] = b1[t];
    __syncthreads();

    int wm = wid & 3, wn = wid >> 2;
    float acc[2][4][4];
#pragma unroll
    for (int mi = 0; mi < 2; mi++)
#pragma unroll
        for (int j = 0; j < 4; j++)
#pragma unroll
            for (int q = 0; q < 4; q++) acc[mi][j][q] = 0.f;

#pragma unroll
    for (int ks = 0; ks < 4; ks++) {
        unsigned ah[2][4], al[2][4];
#pragma unroll
        for (int mi = 0; mi < 2; mi++) {
            unsigned off = (wm * 32 + mi * 16 + (lane & 15)) * 72 + ks * 16 + (lane >> 4) * 8;
            ldsm_x4(smem_u32(xh + off), ah[mi][0], ah[mi][1], ah[mi][2], ah[mi][3]);
            ldsm_x4(smem_u32(xl + off), al[mi][0], al[mi][1], al[mi][2], al[mi][3]);
        }
        unsigned bh[4][2], bl[4][2];
#pragma unroll
        for (int nj = 0; nj < 2; nj++) {
            unsigned off = (ks * 16 + (lane & 15)) * 72 + wn * 32 + nj * 16 + (lane >> 4) * 8;
            unsigned r0, r1, r2, r3;
            ldsm_x4_t(smem_u32(wh + off), r0, r1, r2, r3);
            bh[nj * 2][0] = r0; bh[nj * 2][1] = r1;
            bh[nj * 2 + 1][0] = r2; bh[nj * 2 + 1][1] = r3;
            ldsm_x4_t(smem_u32(wl + off), r0, r1, r2, r3);
            bl[nj * 2][0] = r0; bl[nj * 2][1] = r1;
            bl[nj * 2 + 1][0] = r2; bl[nj * 2 + 1][1] = r3;
        }
#pragma unroll
        for (int mi = 0; mi < 2; mi++)
#pragma unroll
            for (int j = 0; j < 4; j++) {
                mma_bf16(acc[mi][j], ah[mi], bh[j][0], bh[j][1]);
                mma_bf16(acc[mi][j], al[mi], bh[j][0], bh[j][1]);
                mma_bf16(acc[mi][j], ah[mi], bl[j][0], bl[j][1]);
            }
    }

    long base = (long)rt * 128;
#pragma unroll
    for (int mi = 0; mi < 2; mi++) {
#pragma unroll
        for (int j = 0; j < 4; j++) {
            int lr = wm * 32 + mi * 16 + (lane >> 2);
            int lc = wn * 32 + j * 8 + (lane & 3) * 2;
#pragma unroll
            for (int q = 0; q < 4; q++) {
                int rr = lr + (q >> 1) * 8;
                int cc = lc + (q & 1);
                float o = acc[mi][j][q] + b1s[cc];
                long gi = (base + rr) * 64 + cc;
                g_h0[gi]  = o;
                g_h0h[gi] = __float2half_rn(o);
            }
        }
    }
}

// ---------------------------------------------------------------- UNIFIED kernel: role-specialized
//   bids per batch-group of 72: first 64 = adjA blocks (8 rows each), last 8 = duo CTAs (64-row strips).
//   adjA role: stream adj, write fp16 A, flag strip counter (8 producers per strip).
//   duo role: spin on own strip flags (A just written -> L2-hot), gemm1 (64x64) + o0,
//             per-batch ticket barrier (8 CTAs), gemm2 (64x32), reset strip flag.
// Pipeline: uniform-commit + cp_wait<2> — provably complete stage at EVERY iteration
// (fixes the latent tail under-wait that fired under producer/consumer overlap).
// 256 threads, __launch_bounds__(256,3) -> 3 CTAs/SM (matches adjA's proven 6.6 TB/s config).
// duo SMEM: AS 3*64*40*2=15360 | BS 3*32*72*2=13824 | W2 8192 | b2 128 -> 37504 B
#define U_AS   0
#define U_BS   15360
#define U_W2   29184
#define U_B2   37376
#define U_SMEM 37504

__global__ void __launch_bounds__(256, 3) k_main(const float* __restrict__ adj,
                                                 const float* __restrict__ W2,
                                                 const float* __restrict__ b2,
                                                 float* __restrict__ out) {
    extern __shared__ char sm[];
    int t = threadIdx.x, lane = t & 31, wid = t >> 5;
    int group = blockIdx.x / 72;
    int role  = blockIdx.x % 72;

    if (role < 64) {
        // ================= adjA role: block g covers global rows [g*8, g*8+8)
        int g = group * 64 + role;
        long R = (long)g * 8 + wid;
        long b = R >> 9;
        int  n = (int)(R & 511);

        float4 v[4][4];
#pragma unroll
        for (int e = 0; e < 4; e++) {
            const float4* p = (const float4*)(adj + ((b * 4 + e) * 512 + n) * 512) + lane;
#pragma unroll
            for (int c = 0; c < 4; c++) v[e][c] = __ldcs(p + c * 32);
        }
        float inv[4];
#pragma unroll
        for (int e = 0; e < 4; e++) {
            float s = 0.f;
#pragma unroll
            for (int c = 0; c < 4; c++) s += v[e][c].x + v[e][c].y + v[e][c].z + v[e][c].w;
#pragma unroll
            for (int o = 16; o > 0; o >>= 1) s += __shfl_xor_sync(0xffffffffu, s, o);
            inv[e] = 1.0f / (s + 1.0f);
        }
        __half* outp = g_A + (b * 512 + n) * 512;
#pragma unroll
        for (int c = 0; c < 4; c++) {
            float a0 = v[0][c].x * inv[0] + v[1][c].x * inv[1] + v[2][c].x * inv[2] + v[3][c].x * inv[3];
            float a1 = v[0][c].y * inv[0] + v[1][c].y * inv[1] + v[2][c].y * inv[2] + v[3][c].y * inv[3];
            float a2 = v[0][c].z * inv[0] + v[1][c].z * inv[1] + v[2][c].z * inv[2] + v[3][c].z * inv[3];
            float a3 = v[0][c].w * inv[0] + v[1][c].w * inv[1] + v[2][c].w * inv[2] + v[3][c].w * inv[3];
            __half2 p0 = __floats2half2_rn(a0, a1);
            __half2 p1 = __floats2half2_rn(a2, a3);
            uint2 u;
            u.x = *reinterpret_cast<unsigned*>(&p0);
            u.y = *reinterpret_cast<unsigned*>(&p1);
            *reinterpret_cast<uint2*>(outp + c * 128 + lane * 4) = u;
        }
        // release: stores visible, then flag own strip (strip = g/8, 8 producer blocks each)
        __threadfence();
        __syncthreads();
        if (t == 0) atomicAdd(&g_cnt[g >> 3], 1);
        return;
    }

    // ================= duo role: strip d (64 rows), batch b, row0 = rt*64
    int d  = group * 8 + (role - 64);
    int b  = d >> 3, rt = d & 7;
    int row0 = rt * 64;

    __half* AS  = (__half*)(sm + U_AS);    // [3][64][40]
    __half* BS  = (__half*)(sm + U_BS);    // [3][32][72]  (phase2: [3][32][40])
    float*  W2s = (float*)(sm + U_W2);
    float*  b2s = (float*)(sm + U_B2);
    float*  Hs  = (float*)sm;              // reuse AS+BS between phases: [64][68] f32 (17408 B)

    for (int i = t; i < 64 * 32; i += 256) W2s[i] = W2[i];
    if (t < 32) b2s[t] = b2[t];

    // wait for own strip's 8 producer blocks
    if (t == 0) {
        while (atomicAdd(&g_cnt[d], 0) < 8) { }
        __threadfence();
    }
    __syncthreads();

    const __half* Ag  = g_A   + ((long)b * 512 + row0) * 512;
    const __half* Hgh = g_h0h + (long)b * 512 * 64;

    // A stage: 64 rows x 32 cols fp16 = 256 16B-chunks, 1/thread
    auto loadA = [&](int st, int kc) {
        int r = t >> 2, c = t & 3;
        long g = (long)r * 512 + kc * 32 + c * 8;
        unsigned s = st * (64 * 40) + r * 40 + c * 8;
        cp_async16(smem_u32(AS + s), Ag + g);
    };
    // B1 stage: 32 rows x 64 cols = 256 chunks, 1/thread
    auto loadB1 = [&](int st, int kc) {
        int r = t >> 3, c = t & 7;
        long g = (long)(kc * 32 + r) * 64 + c * 8;
        unsigned s = st * (32 * 72) + r * 72 + c * 8;
        cp_async16(smem_u32(BS + s), Hgh + g);
    };

    int wm = wid & 3, wn = wid >> 2;   // 4m x 2n

    // ---------------- Phase 1: 64x64 GEMM (K=512, BK=32, 16 iters) + tanh residual
    {
        float acc[4][4];
#pragma unroll
        for (int j = 0; j < 4; j++)
#pragma unroll
            for (int q = 0; q < 4; q++) acc[j][q] = 0.f;

        loadA(0, 0); loadB1(0, 0); cp_commit();
        loadA(1, 1); loadB1(1, 1); cp_commit();

        for (int kc = 0; kc < 16; kc++) {
            int st = kc % 3;
            // uniform-commit pipeline: one commit per iter (empty at tail), wait<2>
            if (kc + 2 < 16) { loadA((kc + 2) % 3, kc + 2); loadB1((kc + 2) % 3, kc + 2); }
            cp_commit();
            cp_wait<2>();
            __syncthreads();
            const __half* a_s = AS + st * (64 * 40);
            const __half* b_s = BS + st * (32 * 72);
#pragma unroll
            for (int ks = 0; ks < 2; ks++) {
                unsigned af[4];
                {
                    unsigned off = (wm * 16 + (lane & 15)) * 40 + ks * 16 + (lane >> 4) * 8;
                    ldsm_x4(smem_u32(a_s + off), af[0], af[1], af[2], af[3]);
                }
                unsigned bf[4][2];
#pragma unroll
                for (int nj = 0; nj < 2; nj++) {
                    unsigned off = (ks * 16 + (lane & 15)) * 72
                                 + wn * 32 + nj * 16 + (lane >> 4) * 8;
                    unsigned r0, r1, r2, r3;
                    ldsm_x4_t(smem_u32(b_s + off), r0, r1, r2, r3);
                    bf[nj * 2][0] = r0; bf[nj * 2][1] = r1;
                    bf[nj * 2 + 1][0] = r2; bf[nj * 2 + 1][1] = r3;
                }
#pragma unroll
                for (int j = 0; j < 4; j++)
                    mma_f16(acc[j], af, bf[j][0], bf[j][1]);
            }
            __syncthreads();
        }

        // Epilogue 1: hidden = tanh(acc + h0_fp32) -> Hs
        const float* h0g = g_h0 + ((long)b * 512 + row0) * 64;
#pragma unroll
        for (int j = 0; j < 4; j++) {
            int lr = wm * 16 + (lane >> 2);
            int lc = wn * 32 + j * 8 + (lane & 3) * 2;
#pragma unroll
            for (int q = 0; q < 4; q++) {
                int rr = lr + (q >> 1) * 8;
                int cc = lc + (q & 1);
                Hs[rr * 68 + cc] = tanhf(acc[j][q] + h0g[rr * 64 + cc]);
            }
        }
    }
    __syncthreads();

    // Epilogue 2: o0 = Hs @ W2 + b2 (fp32; hidden stays fp32 for precision)
    {
        int r = t >> 2; int dblk = (t & 3) * 8;
        float o[8];
#pragma unroll
        for (int dd = 0; dd < 8; dd++) o[dd] = b2s[dblk + dd];
#pragma unroll
        for (int k = 0; k < 64; k++) {
            float hv = Hs[r * 68 + k];
#pragma unroll
            for (int dd = 0; dd < 8; dd++) o[dd] += hv * W2s[k * 32 + dblk + dd];
        }
        long orow = (long)b * 512 + row0 + r;
#pragma unroll
        for (int dd = 0; dd < 8; dd++) {
            g_o0 [orow * 32 + dblk + dd] = o[dd];
            g_o0h[orow * 32 + dblk + dd] = __float2half_rn(o[dd]);
        }
    }

    // ---------------- per-batch ticket barrier (8 duo CTAs). Monotonic, replay-safe.
    __threadfence();
    __syncthreads();
    if (t == 0) {
        int ticket = atomicAdd(&g_bar[b], 1);
        int target = (ticket / 8 + 1) * 8;
        while (atomicAdd(&g_bar[b], 0) < target) { }
        __threadfence();
    }
    __syncthreads();

    // ---------------- Phase 2: out = tanh(A @ o0 + o0), 64x32, same A strip (L2-hot)
    const __half* Ogh = g_o0h + (long)b * 512 * 32;
    auto loadB2 = [&](int st, int kc) {
        if (t < 128) {
            int r = t >> 2, c = t & 3;
            long g = (long)(kc * 32 + r) * 32 + c * 8;
            unsigned s = st * (32 * 40) + r * 40 + c * 8;
            cp_async16(smem_u32(BS + s), Ogh + g);
        }
    };

    {
        float acc[2][4];
#pragma unroll
        for (int j = 0; j < 2; j++)
#pragma unroll
            for (int q = 0; q < 4; q++) acc[j][q] = 0.f;

        loadA(0, 0); loadB2(0, 0); cp_commit();
        loadA(1, 1); loadB2(1, 1); cp_commit();

        for (int kc = 0; kc < 16; kc++) {
            int st = kc % 3;
            if (kc + 2 < 16) { loadA((kc + 2) % 3, kc + 2); loadB2((kc + 2) % 3, kc + 2); }
            cp_commit();
            cp_wait<2>();
            __syncthreads();
            const __half* a_s = AS + st * (64 * 40);
            const __half* b_s = BS + st * (32 * 40);
#pragma unroll
            for (int ks = 0; ks < 2; ks++) {
                unsigned af[4];
                {
                    unsigned off = (wm * 16 + (lane & 15)) * 40 + ks * 16 + (lane >> 4) * 8;
                    ldsm_x4(smem_u32(a_s + off), af[0], af[1], af[2], af[3]);
                }
                unsigned bf[2][2];
                {
                    unsigned off = (ks * 16 + (lane & 15)) * 40 + wn * 16 + (lane >> 4) * 8;
                    unsigned r0, r1, r2, r3;
                    ldsm_x4_t(smem_u32(b_s + off), r0, r1, r2, r3);
                    bf[0][0] = r0; bf[0][1] = r1;
                    bf[1][0] = r2; bf[1][1] = r3;
                }
#pragma unroll
                for (int j = 0; j < 2; j++)
                    mma_f16(acc[j], af, bf[j][0], bf[j][1]);
            }
            __syncthreads();
        }

        // Epilogue: out = tanh(acc + o0_fp32)
        const float* o0g = g_o0 + ((long)b * 512 + row0) * 32;
        float*       og  = out  + ((long)b * 512 + row0) * 32;
#pragma unroll
        for (int j = 0; j < 2; j++) {
            int lr = wm * 16 + (lane >> 2);
            int lc = wn * 16 + j * 8 + (lane & 3) * 2;
#pragma unroll
            for (int q = 0; q < 4; q++) {
                int rr = lr + (q >> 1) * 8;
                int cc = lc + (q & 1);
                og[rr * 32 + cc] = tanhf(acc[j][q] + o0g[rr * 32 + cc]);
            }
        }
    }

    // reset own strip counter for next launch/replay (single writer per strip)
    __syncthreads();
    if (t == 0) atomicExch(&g_cnt[d], 0);
}

// ---------------------------------------------------------------- launcher
extern "C" void kernel_launch(void* const* d_in, const int* in_sizes, int n_in,
                              void* d_out, int out_size) {
    const float* x   = (const float*)d_in[0];
    const float* adj = (const float*)d_in[1];
    const float* W1  = (const float*)d_in[2];
    const float* b1  = (const float*)d_in[3];
    const float* W2  = (const float*)d_in[4];
    const float* b2  = (const float*)d_in[5];
    float* out = (float*)d_out;

    (void)in_sizes; (void)n_in; (void)out_size;

    cudaFuncSetAttribute(k_h0mma, cudaFuncAttributeMaxDynamicSharedMemorySize, H_SMEM);

    // h0 first (duo CTAs consume it from the very first batch); then the unified
    // stream+GEMM kernel: adjA blocks and duo consumers interleaved per batch.
    k_h0mma<<<256, 256, H_SMEM>>>(x, W1, b1);
    k_main <<<64 * 72, 256, U_SMEM>>>(adj, W2, b2, out);
}

// round 12
// speedup vs baseline: 1.0741x; 1.0741x over previous
#include <cuda_runtime.h>
#include <cuda_bf16.h>
#include <cuda_fp16.h>
#include <cstdint>

// Problem constants
#define B_   64
#define E_   4
#define N_   512
#define DIN_ 64
#define D0_  64
#define D1_  32

// Scratch (static __device__ arrays — allocation-free per harness rules)
__device__ __align__(256) __half g_A  [(size_t)B_ * N_ * N_];   // 32 MB fp16 A (fits L2)
__device__ __align__(256) float  g_h0 [(size_t)B_ * N_ * D0_];  // 8 MB (fp32 residual)
__device__ __align__(256) __half g_h0h[(size_t)B_ * N_ * D0_];  // 4 MB (fp16 operand)
__device__ __align__(256) float  g_o0 [(size_t)B_ * N_ * D1_];  // 4 MB (fp32 residual)
__device__ __align__(256) __half g_o0h[(size_t)B_ * N_ * D1_];  // 2 MB (fp16 operand)

// ---------------------------------------------------------------- helpers
__device__ __forceinline__ unsigned smem_u32(const void* p) {
    return (unsigned)__cvta_generic_to_shared(p);
}
__device__ __forceinline__ void cp_async16(unsigned s, const void* g) {
    asm volatile("cp.async.cg.shared.global [%0], [%1], 16;\n" :: "r"(s), "l"(g));
}
__device__ __forceinline__ void cp_async16_pol(unsigned s, const void* g, uint64_t pol) {
    asm volatile("cp.async.cg.shared.global.L2::cache_hint [%0], [%1], 16, %2;\n"
                 :: "r"(s), "l"(g), "l"(pol));
}
__device__ __forceinline__ void cp_commit() {
    asm volatile("cp.async.commit_group;\n");
}
template <int NWAIT>
__device__ __forceinline__ void cp_wait() {
    asm volatile("cp.async.wait_group %0;\n" :: "n"(NWAIT));
}
__device__ __forceinline__ uint64_t mk_evict_last_policy() {
    uint64_t p;
    asm("createpolicy.fractional.L2::evict_last.b64 %0, 1.0;\n" : "=l"(p));
    return p;
}
__device__ __forceinline__ void ldsm_x4(unsigned addr, unsigned& r0, unsigned& r1,
                                        unsigned& r2, unsigned& r3) {
    asm volatile("ldmatrix.sync.aligned.m8n8.x4.shared.b16 {%0,%1,%2,%3}, [%4];\n"
                 : "=r"(r0), "=r"(r1), "=r"(r2), "=r"(r3) : "r"(addr));
}
__device__ __forceinline__ void ldsm_x4_t(unsigned addr, unsigned& r0, unsigned& r1,
                                          unsigned& r2, unsigned& r3) {
    asm volatile("ldmatrix.sync.aligned.m8n8.x4.trans.shared.b16 {%0,%1,%2,%3}, [%4];\n"
                 : "=r"(r0), "=r"(r1), "=r"(r2), "=r"(r3) : "r"(addr));
}
__device__ __forceinline__ void mma_f16(float c[4], const unsigned a[4],
                                        unsigned b0, unsigned b1) {
    asm volatile(
        "mma.sync.aligned.m16n8k16.row.col.f32.f16.f16.f32 "
        "{%0,%1,%2,%3},{%4,%5,%6,%7},{%8,%9},{%0,%1,%2,%3};\n"
        : "+f"(c[0]), "+f"(c[1]), "+f"(c[2]), "+f"(c[3])
        : "r"(a[0]), "r"(a[1]), "r"(a[2]), "r"(a[3]), "r"(b0), "r"(b1));
}
__device__ __forceinline__ void mma_bf16(float c[4], const unsigned a[4],
                                         unsigned b0, unsigned b1) {
    asm volatile(
        "mma.sync.aligned.m16n8k16.row.col.f32.bf16.bf16.f32 "
        "{%0,%1,%2,%3},{%4,%5,%6,%7},{%8,%9},{%0,%1,%2,%3};\n"
        : "+f"(c[0]), "+f"(c[1]), "+f"(c[2]), "+f"(c[3])
        : "r"(a[0]), "r"(a[1]), "r"(a[2]), "r"(a[3]), "r"(b0), "r"(b1));
}
__device__ __forceinline__ void split_bf16(float a, __nv_bfloat16& hi, __nv_bfloat16& lo) {
    hi = __float2bfloat16(a);
    lo = __float2bfloat16(a - __bfloat162float(hi));
}
__device__ __forceinline__ void st_evl_u2(void* p, uint2 v, uint64_t pol) {
    asm volatile("st.global.L2::cache_hint.v2.u32 [%0], {%1,%2}, %3;\n"
                 :: "l"(p), "r"(v.x), "r"(v.y), "l"(pol) : "memory");
}

// ---------------------------------------------------------------- STREAM kernel (role-split):
//   bids 0..255    : h0 = x@W1 + b1 (tensor-core, split-bf16) — independent of adj, overlaps the stream.
//   bids 256..4351 : adjA blocks — A = sum_e adj_e/(rowsum_e+1), fp16 store with evict_last (A fits L2).
// __launch_bounds__(256,3): adjA role is reg-limited to 3 CTAs/SM (proven 6.6 TB/s config);
// smem 55.5KB x 3 = 166KB < 228KB so smem doesn't reduce it.
#define H_XH   0
#define H_XL   18432
#define H_WH   36864
#define H_WL   46080
#define H_B1   55296
#define H_SMEM 55552

__global__ void __launch_bounds__(256, 3) k_stream(const float* __restrict__ adj,
                                                   const float* __restrict__ x,
                                                   const float* __restrict__ W1,
                                                   const float* __restrict__ b1) {
    extern __shared__ char sm[];
    int t = threadIdx.x, lane = t & 31, wid = t >> 5;

    if (blockIdx.x >= 256) {
        // ================= adjA role: block g covers global rows [g*8, g*8+8)
        int g = blockIdx.x - 256;
        long R = (long)g * 8 + wid;
        long b = R >> 9;
        int  n = (int)(R & 511);
        uint64_t pol = mk_evict_last_policy();

        float4 v[4][4];
#pragma unroll
        for (int e = 0; e < 4; e++) {
            const float4* p = (const float4*)(adj + ((b * 4 + e) * 512 + n) * 512) + lane;
#pragma unroll
            for (int c = 0; c < 4; c++) v[e][c] = __ldcs(p + c * 32);
        }
        float inv[4];
#pragma unroll
        for (int e = 0; e < 4; e++) {
            float s = 0.f;
#pragma unroll
            for (int c = 0; c < 4; c++) s += v[e][c].x + v[e][c].y + v[e][c].z + v[e][c].w;
#pragma unroll
            for (int o = 16; o > 0; o >>= 1) s += __shfl_xor_sync(0xffffffffu, s, o);
            inv[e] = 1.0f / (s + 1.0f);
        }
        __half* outp = g_A + (b * 512 + n) * 512;
#pragma unroll
        for (int c = 0; c < 4; c++) {
            float a0 = v[0][c].x * inv[0] + v[1][c].x * inv[1] + v[2][c].x * inv[2] + v[3][c].x * inv[3];
            float a1 = v[0][c].y * inv[0] + v[1][c].y * inv[1] + v[2][c].y * inv[2] + v[3][c].y * inv[3];
            float a2 = v[0][c].z * inv[0] + v[1][c].z * inv[1] + v[2][c].z * inv[2] + v[3][c].z * inv[3];
            float a3 = v[0][c].w * inv[0] + v[1][c].w * inv[1] + v[2][c].w * inv[2] + v[3][c].w * inv[3];
            __half2 p0 = __floats2half2_rn(a0, a1);
            __half2 p1 = __floats2half2_rn(a2, a3);
            uint2 u;
            u.x = *reinterpret_cast<unsigned*>(&p0);
            u.y = *reinterpret_cast<unsigned*>(&p1);
            st_evl_u2(outp + c * 128 + lane * 4, u, pol);
        }
        return;
    }

    // ================= h0 role: tile rt = blockIdx.x (128 rows x 64)
    int rt = blockIdx.x;
    __nv_bfloat16* xh = (__nv_bfloat16*)(sm + H_XH);   // [128][72]
    __nv_bfloat16* xl = (__nv_bfloat16*)(sm + H_XL);
    __nv_bfloat16* wh = (__nv_bfloat16*)(sm + H_WH);   // [64][72]
    __nv_bfloat16* wl = (__nv_bfloat16*)(sm + H_WL);
    float*        b1s = (float*)(sm + H_B1);

    const float* xg = x + (long)rt * 128 * 64;

#pragma unroll
    for (int i = 0; i < 8; i++) {
        int idx = t + i * 256;
        int r = idx >> 4, c = (idx & 15) * 4;
        float4 v = *(const float4*)(xg + r * 64 + c);
        __nv_bfloat162 h01, h23, l01, l23;
        split_bf16(v.x, h01.x, l01.x); split_bf16(v.y, h01.y, l01.y);
        split_bf16(v.z, h23.x, l23.x); split_bf16(v.w, h23.y, l23.y);
        uint2 uh, ul;
        uh.x = *reinterpret_cast<unsigned*>(&h01); uh.y = *reinterpret_cast<unsigned*>(&h23);
        ul.x = *reinterpret_cast<unsigned*>(&l01); ul.y = *reinterpret_cast<unsigned*>(&l23);
        *reinterpret_cast<uint2*>(xh + r * 72 + c) = uh;
        *reinterpret_cast<uint2*>(xl + r * 72 + c) = ul;
    }
#pragma unroll
    for (int i = 0; i < 4; i++) {
        int idx = t + i * 256;
        int r = idx >> 4, c = (idx & 15) * 4;
        float4 v = *(const float4*)(W1 + r * 64 + c);
        __nv_bfloat162 h01, h23, l01, l23;
        split_bf16(v.x, h01.x, l01.x); split_bf16(v.y, h01.y, l01.y);
        split_bf16(v.z, h23.x, l23.x); split_bf16(v.w, h23.y, l23.y);
        uint2 uh, ul;
        uh.x = *reinterpret_cast<unsigned*>(&h01); uh.y = *reinterpret_cast<unsigned*>(&h23);
        ul.x = *reinterpret_cast<unsigned*>(&l01); ul.y = *reinterpret_cast<unsigned*>(&l23);
        *reinterpret_cast<uint2*>(wh + r * 72 + c) = uh;
        *reinterpret_cast<uint2*>(wl + r * 72 + c) = ul;
    }
    if (t < 64) b1s[t] = b1[t];
    __syncthreads();

    int wm = wid & 3, wn = wid >> 2;
    float acc[2][4][4];
#pragma unroll
    for (int mi = 0; mi < 2; mi++)
#pragma unroll
        for (int j = 0; j < 4; j++)
#pragma unroll
            for (int q = 0; q < 4; q++) acc[mi][j][q] = 0.f;

#pragma unroll
    for (int ks = 0; ks < 4; ks++) {
        unsigned ah[2][4], al[2][4];
#pragma unroll
        for (int mi = 0; mi < 2; mi++) {
            unsigned off = (wm * 32 + mi * 16 + (lane & 15)) * 72 + ks * 16 + (lane >> 4) * 8;
            ldsm_x4(smem_u32(xh + off), ah[mi][0], ah[mi][1], ah[mi][2], ah[mi][3]);
            ldsm_x4(smem_u32(xl + off), al[mi][0], al[mi][1], al[mi][2], al[mi][3]);
        }
        unsigned bh[4][2], bl[4][2];
#pragma unroll
        for (int nj = 0; nj < 2; nj++) {
            unsigned off = (ks * 16 + (lane & 15)) * 72 + wn * 32 + nj * 16 + (lane >> 4) * 8;
            unsigned r0, r1, r2, r3;
            ldsm_x4_t(smem_u32(wh + off), r0, r1, r2, r3);
            bh[nj * 2][0] = r0; bh[nj * 2][1] = r1;
            bh[nj * 2 + 1][0] = r2; bh[nj * 2 + 1][1] = r3;
            ldsm_x4_t(smem_u32(wl + off), r0, r1, r2, r3);
            bl[nj * 2][0] = r0; bl[nj * 2][1] = r1;
            bl[nj * 2 + 1][0] = r2; bl[nj * 2 + 1][1] = r3;
        }
#pragma unroll
        for (int mi = 0; mi < 2; mi++)
#pragma unroll
            for (int j = 0; j < 4; j++) {
                mma_bf16(acc[mi][j], ah[mi], bh[j][0], bh[j][1]);
                mma_bf16(acc[mi][j], al[mi], bh[j][0], bh[j][1]);
                mma_bf16(acc[mi][j], ah[mi], bl[j][0], bl[j][1]);
            }
    }

    long base = (long)rt * 128;
#pragma unroll
    for (int mi = 0; mi < 2; mi++) {
#pragma unroll
        for (int j = 0; j < 4; j++) {
            int lr = wm * 32 + mi * 16 + (lane >> 2);
            int lc = wn * 32 + j * 8 + (lane & 3) * 2;
#pragma unroll
            for (int q = 0; q < 4; q++) {
                int rr = lr + (q >> 1) * 8;
                int cc = lc + (q & 1);
                float o = acc[mi][j][q] + b1s[cc];
                long gi = (base + rr) * 64 + cc;
                g_h0[gi]  = o;
                g_h0h[gi] = __float2half_rn(o);
            }
        }
    }
}

// ---------------------------------------------------------------- GEMM1: hidden = tanh(A@h0 + h0); o0 = hidden@W2 + b2
// 64-row tiles x 64 cols, K=512, BK=32, 3-stage FIXED pipeline. Grid (8,64)=512 CTAs.
// __launch_bounds__(256,3) -> 3 CTAs/SM, 24 warps/SM (R11-proven 80 regs at this shape).
// SMEM: AS 3*64*40*2=15360 | BS 3*32*72*2=13824 | W2 8192 | b2 128 -> 37504 B
#define G1_AS   0
#define G1_BS   15360
#define G1_W2   29184
#define G1_B2   37376
#define G1_SMEM 37504

__global__ void __launch_bounds__(256, 3) k_g1(const float* __restrict__ W2,
                                               const float* __restrict__ b2) {
    extern __shared__ char sm[];
    __half* AS  = (__half*)(sm + G1_AS);   // [3][64][40]
    __half* BS  = (__half*)(sm + G1_BS);   // [3][32][72]
    float*  W2s = (float*)(sm + G1_W2);
    float*  b2s = (float*)(sm + G1_B2);
    float*  Hs  = (float*)sm;              // reuse after mainloop: [64][68] f32

    int t = threadIdx.x, lane = t & 31, wid = t >> 5;
    int rt = blockIdx.x, b = blockIdx.y;
    int row0 = rt * 64;
    uint64_t pol = mk_evict_last_policy();
    const __half* Ag  = g_A   + ((long)b * 512 + row0) * 512;
    const __half* Hgh = g_h0h + (long)b * 512 * 64;

    for (int i = t; i < 64 * 32; i += 256) W2s[i] = W2[i];
    if (t < 32) b2s[t] = b2[t];

    auto loadA = [&](int st, int kc) {      // 64x32 fp16 = 256 chunks, 1/thread
        int r = t >> 2, c = t & 3;
        long g = (long)r * 512 + kc * 32 + c * 8;
        unsigned s = st * (64 * 40) + r * 40 + c * 8;
        cp_async16_pol(smem_u32(AS + s), Ag + g, pol);
    };
    auto loadB = [&](int st, int kc) {      // 32x64 = 256 chunks, 1/thread
        int r = t >> 3, c = t & 7;
        long g = (long)(kc * 32 + r) * 64 + c * 8;
        unsigned s = st * (32 * 72) + r * 72 + c * 8;
        cp_async16(smem_u32(BS + s), Hgh + g);
    };

    int wm = wid & 3, wn = wid >> 2;   // 4m x 2n, warp tile 16x32

    float acc[4][4];
#pragma unroll
    for (int j = 0; j < 4; j++)
#pragma unroll
        for (int q = 0; q < 4; q++) acc[j][q] = 0.f;

    loadA(0, 0); loadB(0, 0); cp_commit();
    loadA(1, 1); loadB(1, 1); cp_commit();

    for (int kc = 0; kc < 16; kc++) {
        int st = kc % 3;
        // uniform-commit pipeline: one commit/iter (empty at tail), wait<2> => stage kc complete
        if (kc + 2 < 16) { loadA((kc + 2) % 3, kc + 2); loadB((kc + 2) % 3, kc + 2); }
        cp_commit();
        cp_wait<2>();
        __syncthreads();
        const __half* a_s = AS + st * (64 * 40);
        const __half* b_s = BS + st * (32 * 72);
#pragma unroll
        for (int ks = 0; ks < 2; ks++) {
            unsigned af[4];
            {
                unsigned off = (wm * 16 + (lane & 15)) * 40 + ks * 16 + (lane >> 4) * 8;
                ldsm_x4(smem_u32(a_s + off), af[0], af[1], af[2], af[3]);
            }
            unsigned bf[4][2];
#pragma unroll
            for (int nj = 0; nj < 2; nj++) {
                unsigned off = (ks * 16 + (lane & 15)) * 72 + wn * 32 + nj * 16 + (lane >> 4) * 8;
                unsigned r0, r1, r2, r3;
                ldsm_x4_t(smem_u32(b_s + off), r0, r1, r2, r3);
                bf[nj * 2][0] = r0; bf[nj * 2][1] = r1;
                bf[nj * 2 + 1][0] = r2; bf[nj * 2 + 1][1] = r3;
            }
#pragma unroll
            for (int j = 0; j < 4; j++)
                mma_f16(acc[j], af, bf[j][0], bf[j][1]);
        }
        __syncthreads();
    }

    // Epilogue 1: hidden = tanh(acc + h0_fp32) -> Hs
    const float* h0g = g_h0 + ((long)b * 512 + row0) * 64;
#pragma unroll
    for (int j = 0; j < 4; j++) {
        int lr = wm * 16 + (lane >> 2);
        int lc = wn * 32 + j * 8 + (lane & 3) * 2;
#pragma unroll
        for (int q = 0; q < 4; q++) {
            int rr = lr + (q >> 1) * 8;
            int cc = lc + (q & 1);
            Hs[rr * 68 + cc] = tanhf(acc[j][q] + h0g[rr * 64 + cc]);
        }
    }
    __syncthreads();

    // Epilogue 2: o0 = Hs @ W2 + b2 (fp32; hidden stays fp32 for precision)
    {
        int r = t >> 2; int dblk = (t & 3) * 8;
        float o[8];
#pragma unroll
        for (int dd = 0; dd < 8; dd++) o[dd] = b2s[dblk + dd];
#pragma unroll
        for (int k = 0; k < 64; k++) {
            float hv = Hs[r * 68 + k];
#pragma unroll
            for (int dd = 0; dd < 8; dd++) o[dd] += hv * W2s[k * 32 + dblk + dd];
        }
        long orow = (long)b * 512 + row0 + r;
#pragma unroll
        for (int dd = 0; dd < 8; dd++) {
            g_o0 [orow * 32 + dblk + dd] = o[dd];
            g_o0h[orow * 32 + dblk + dd] = __float2half_rn(o[dd]);
        }
    }
}

// ---------------------------------------------------------------- GEMM2: out = tanh(A@o0 + o0)
// 64-row tiles x 32 cols, K=512, BK=32, 3-stage FIXED pipeline. Grid (8,64)=512 CTAs.
// SMEM: AS 15360 | BS 3*32*40*2=7680 -> 23040 B. (256,3).
#define G2_AS   0
#define G2_BS   15360
#define G2_SMEM 23040

__global__ void __launch_bounds__(256, 3) k_g2(float* __restrict__ out) {
    extern __shared__ char sm[];
    __half* AS = (__half*)(sm + G2_AS);    // [3][64][40]
    __half* BS = (__half*)(sm + G2_BS);    // [3][32][40]

    int t = threadIdx.x, lane = t & 31, wid = t >> 5;
    int rt = blockIdx.x, b = blockIdx.y;
    int row0 = rt * 64;
    const __half* Ag  = g_A   + ((long)b * 512 + row0) * 512;
    const __half* Ogh = g_o0h + (long)b * 512 * 32;

    auto loadA = [&](int st, int kc) {      // 64x32 fp16 = 256 chunks, 1/thread
        int r = t >> 2, c = t & 3;
        long g = (long)r * 512 + kc * 32 + c * 8;
        unsigned s = st * (64 * 40) + r * 40 + c * 8;
        cp_async16(smem_u32(AS + s), Ag + g);
    };
    auto loadB = [&](int st, int kc) {      // 32x32 = 128 chunks
        if (t < 128) {
            int r = t >> 2, c = t & 3;
            long g = (long)(kc * 32 + r) * 32 + c * 8;
            unsigned s = st * (32 * 40) + r * 40 + c * 8;
            cp_async16(smem_u32(BS + s), Ogh + g);
        }
    };

    int wm = wid & 3, wn = wid >> 2;   // 4m x 2n, warp tile 16x16

    float acc[2][4];
#pragma unroll
    for (int j = 0; j < 2; j++)
#pragma unroll
        for (int q = 0; q < 4; q++) acc[j][q] = 0.f;

    loadA(0, 0); loadB(0, 0); cp_commit();
    loadA(1, 1); loadB(1, 1); cp_commit();

    for (int kc = 0; kc < 16; kc++) {
        int st = kc % 3;
        if (kc + 2 < 16) { loadA((kc + 2) % 3, kc + 2); loadB((kc + 2) % 3, kc + 2); }
        cp_commit();
        cp_wait<2>();
        __syncthreads();
        const __half* a_s = AS + st * (64 * 40);
        const __half* b_s = BS + st * (32 * 40);
#pragma unroll
        for (int ks = 0; ks < 2; ks++) {
            unsigned af[4];
            {
                unsigned off = (wm * 16 + (lane & 15)) * 40 + ks * 16 + (lane >> 4) * 8;
                ldsm_x4(smem_u32(a_s + off), af[0], af[1], af[2], af[3]);
            }
            unsigned bf[2][2];
            {
                unsigned off = (ks * 16 + (lane & 15)) * 40 + wn * 16 + (lane >> 4) * 8;
                unsigned r0, r1, r2, r3;
                ldsm_x4_t(smem_u32(b_s + off), r0, r1, r2, r3);
                bf[0][0] = r0; bf[0][1] = r1;
                bf[1][0] = r2; bf[1][1] = r3;
            }
#pragma unroll
            for (int j = 0; j < 2; j++)
                mma_f16(acc[j], af, bf[j][0], bf[j][1]);
        }
        __syncthreads();
    }

    // Epilogue: out = tanh(acc + o0_fp32)
    const float* o0g = g_o0 + ((long)b * 512 + row0) * 32;
    float*       og  = out  + ((long)b * 512 + row0) * 32;
#pragma unroll
    for (int j = 0; j < 2; j++) {
        int lr = wm * 16 + (lane >> 2);
        int lc = wn * 16 + j * 8 + (lane & 3) * 2;
#pragma unroll
        for (int q = 0; q < 4; q++) {
            int rr = lr + (q >> 1) * 8;
            int cc = lc + (q & 1);
            og[rr * 32 + cc] = tanhf(acc[j][q] + o0g[rr * 32 + cc]);
        }
    }
}

// ---------------------------------------------------------------- launcher
extern "C" void kernel_launch(void* const* d_in, const int* in_sizes, int n_in,
                              void* d_out, int out_size) {
    const float* x   = (const float*)d_in[0];
    const float* adj = (const float*)d_in[1];
    const float* W1  = (const float*)d_in[2];
    const float* b1  = (const float*)d_in[3];
    const float* W2  = (const float*)d_in[4];
    const float* b2  = (const float*)d_in[5];
    float* out = (float*)d_out;

    (void)in_sizes; (void)n_in; (void)out_size;

    cudaFuncSetAttribute(k_stream, cudaFuncAttributeMaxDynamicSharedMemorySize, H_SMEM);
    cudaFuncSetAttribute(k_g1,     cudaFuncAttributeMaxDynamicSharedMemorySize, G1_SMEM);
    cudaFuncSetAttribute(k_g2,     cudaFuncAttributeMaxDynamicSharedMemorySize, G2_SMEM);

    // Stream kernel: h0 role (256 CTAs, independent) overlapped with adjA stream (4096 blocks).
    // GEMMs after: A (32MB fp16) is fully L2-resident via evict_last stores/loads.
    k_stream<<<4096 + 256, 256, H_SMEM>>>(adj, x, W1, b1);
    k_g1    <<<dim3(8, 64), 256, G1_SMEM>>>(W2, b2);
    k_g2    <<<dim3(8, 64), 256, G2_SMEM>>>(out);
}

// round 13
// speedup vs baseline: 1.2242x; 1.1398x over previous
#include <cuda_runtime.h>
#include <cuda_bf16.h>
#include <cuda_fp16.h>
#include <cstdint>

// Problem constants
#define B_   64
#define E_   4
#define N_   512
#define DIN_ 64
#define D0_  64
#define D1_  32

// Scratch (static __device__ arrays — allocation-free per harness rules)
__device__ __align__(256) __half g_A  [(size_t)B_ * N_ * N_];   // 32 MB fp16 A (fits L2)
__device__ __align__(256) float  g_h0 [(size_t)B_ * N_ * D0_];  // 8 MB (fp32 residual)
__device__ __align__(256) __half g_h0h[(size_t)B_ * N_ * D0_];  // 4 MB (fp16 operand)
__device__ __align__(256) float  g_o0 [(size_t)B_ * N_ * D1_];  // 4 MB (fp32 residual)
__device__ __align__(256) __half g_o0h[(size_t)B_ * N_ * D1_];  // 2 MB (fp16 operand)
__device__ int g_bar[B_];   // per-batch monotonic ticket counters (never reset; replay-safe)

// ---------------------------------------------------------------- helpers
__device__ __forceinline__ unsigned smem_u32(const void* p) {
    return (unsigned)__cvta_generic_to_shared(p);
}
__device__ __forceinline__ void cp_async16(unsigned s, const void* g) {
    asm volatile("cp.async.cg.shared.global [%0], [%1], 16;\n" :: "r"(s), "l"(g));
}
__device__ __forceinline__ void cp_async16_pol(unsigned s, const void* g, uint64_t pol) {
    asm volatile("cp.async.cg.shared.global.L2::cache_hint [%0], [%1], 16, %2;\n"
                 :: "r"(s), "l"(g), "l"(pol));
}
__device__ __forceinline__ void cp_commit() {
    asm volatile("cp.async.commit_group;\n");
}
template <int NWAIT>
__device__ __forceinline__ void cp_wait() {
    asm volatile("cp.async.wait_group %0;\n" :: "n"(NWAIT));
}
__device__ __forceinline__ uint64_t mk_evict_last_policy() {
    uint64_t p;
    asm("createpolicy.fractional.L2::evict_last.b64 %0, 1.0;\n" : "=l"(p));
    return p;
}
__device__ __forceinline__ void ldsm_x4(unsigned addr, unsigned& r0, unsigned& r1,
                                        unsigned& r2, unsigned& r3) {
    asm volatile("ldmatrix.sync.aligned.m8n8.x4.shared.b16 {%0,%1,%2,%3}, [%4];\n"
                 : "=r"(r0), "=r"(r1), "=r"(r2), "=r"(r3) : "r"(addr));
}
__device__ __forceinline__ void ldsm_x4_t(unsigned addr, unsigned& r0, unsigned& r1,
                                          unsigned& r2, unsigned& r3) {
    asm volatile("ldmatrix.sync.aligned.m8n8.x4.trans.shared.b16 {%0,%1,%2,%3}, [%4];\n"
                 : "=r"(r0), "=r"(r1), "=r"(r2), "=r"(r3) : "r"(addr));
}
__device__ __forceinline__ void mma_f16(float c[4], const unsigned a[4],
                                        unsigned b0, unsigned b1) {
    asm volatile(
        "mma.sync.aligned.m16n8k16.row.col.f32.f16.f16.f32 "
        "{%0,%1,%2,%3},{%4,%5,%6,%7},{%8,%9},{%0,%1,%2,%3};\n"
        : "+f"(c[0]), "+f"(c[1]), "+f"(c[2]), "+f"(c[3])
        : "r"(a[0]), "r"(a[1]), "r"(a[2]), "r"(a[3]), "r"(b0), "r"(b1));
}
__device__ __forceinline__ void mma_bf16(float c[4], const unsigned a[4],
                                         unsigned b0, unsigned b1) {
    asm volatile(
        "mma.sync.aligned.m16n8k16.row.col.f32.bf16.bf16.f32 "
        "{%0,%1,%2,%3},{%4,%5,%6,%7},{%8,%9},{%0,%1,%2,%3};\n"
        : "+f"(c[0]), "+f"(c[1]), "+f"(c[2]), "+f"(c[3])
        : "r"(a[0]), "r"(a[1]), "r"(a[2]), "r"(a[3]), "r"(b0), "r"(b1));
}
__device__ __forceinline__ void split_bf16(float a, __nv_bfloat16& hi, __nv_bfloat16& lo) {
    hi = __float2bfloat16(a);
    lo = __float2bfloat16(a - __bfloat162float(hi));
}
__device__ __forceinline__ void st_evl_u2(void* p, uint2 v, uint64_t pol) {
    asm volatile("st.global.L2::cache_hint.v2.u32 [%0], {%1,%2}, %3;\n"
                 :: "l"(p), "r"(v.x), "r"(v.y), "l"(pol) : "memory");
}

// ---------------------------------------------------------------- kernel 1: h0 = x @ W1 + b1  (tensor-core, split-bf16 internally)
#define H_XH   0
#define H_XL   18432
#define H_WH   36864
#define H_WL   46080
#define H_B1   55296
#define H_SMEM 55552

__global__ void __launch_bounds__(256) k_h0mma(const float* __restrict__ x,
                                               const float* __restrict__ W1,
                                               const float* __restrict__ b1) {
    extern __shared__ char sm[];
    __nv_bfloat16* xh = (__nv_bfloat16*)(sm + H_XH);   // [128][72]
    __nv_bfloat16* xl = (__nv_bfloat16*)(sm + H_XL);
    __nv_bfloat16* wh = (__nv_bfloat16*)(sm + H_WH);   // [64][72]
    __nv_bfloat16* wl = (__nv_bfloat16*)(sm + H_WL);
    float*        b1s = (float*)(sm + H_B1);

    int t = threadIdx.x, lane = t & 31, wid = t >> 5;
    int rt = blockIdx.x;
    const float* xg = x + (long)rt * 128 * 64;

#pragma unroll
    for (int i = 0; i < 8; i++) {
        int idx = t + i * 256;
        int r = idx >> 4, c = (idx & 15) * 4;
        float4 v = *(const float4*)(xg + r * 64 + c);
        __nv_bfloat162 h01, h23, l01, l23;
        split_bf16(v.x, h01.x, l01.x); split_bf16(v.y, h01.y, l01.y);
        split_bf16(v.z, h23.x, l23.x); split_bf16(v.w, h23.y, l23.y);
        uint2 uh, ul;
        uh.x = *reinterpret_cast<unsigned*>(&h01); uh.y = *reinterpret_cast<unsigned*>(&h23);
        ul.x = *reinterpret_cast<unsigned*>(&l01); ul.y = *reinterpret_cast<unsigned*>(&l23);
        *reinterpret_cast<uint2*>(xh + r * 72 + c) = uh;
        *reinterpret_cast<uint2*>(xl + r * 72 + c) = ul;
    }
#pragma unroll
    for (int i = 0; i < 4; i++) {
        int idx = t + i * 256;
        int r = idx >> 4, c = (idx & 15) * 4;
        float4 v = *(const float4*)(W1 + r * 64 + c);
        __nv_bfloat162 h01, h23, l01, l23;
        split_bf16(v.x, h01.x, l01.x); split_bf16(v.y, h01.y, l01.y);
        split_bf16(v.z, h23.x, l23.x); split_bf16(v.w, h23.y, l23.y);
        uint2 uh, ul;
        uh.x = *reinterpret_cast<unsigned*>(&h01); uh.y = *reinterpret_cast<unsigned*>(&h23);
        ul.x = *reinterpret_cast<unsigned*>(&l01); ul.y = *reinterpret_cast<unsigned*>(&l23);
        *reinterpret_cast<uint2*>(wh + r * 72 + c) = uh;
        *reinterpret_cast<uint2*>(wl + r * 72 + c) = ul;
    }
    if (t < 64) b1s[t] = b1[t];
    __syncthreads();

    int wm = wid & 3, wn = wid >> 2;
    float acc[2][4][4];
#pragma unroll
    for (int mi = 0; mi < 2; mi++)
#pragma unroll
        for (int j = 0; j < 4; j++)
#pragma unroll
            for (int q = 0; q < 4; q++) acc[mi][j][q] = 0.f;

#pragma unroll
    for (int ks = 0; ks < 4; ks++) {
        unsigned ah[2][4], al[2][4];
#pragma unroll
        for (int mi = 0; mi < 2; mi++) {
            unsigned off = (wm * 32 + mi * 16 + (lane & 15)) * 72 + ks * 16 + (lane >> 4) * 8;
            ldsm_x4(smem_u32(xh + off), ah[mi][0], ah[mi][1], ah[mi][2], ah[mi][3]);
            ldsm_x4(smem_u32(xl + off), al[mi][0], al[mi][1], al[mi][2], al[mi][3]);
        }
        unsigned bh[4][2], bl[4][2];
#pragma unroll
        for (int nj = 0; nj < 2; nj++) {
            unsigned off = (ks * 16 + (lane & 15)) * 72 + wn * 32 + nj * 16 + (lane >> 4) * 8;
            unsigned r0, r1, r2, r3;
            ldsm_x4_t(smem_u32(wh + off), r0, r1, r2, r3);
            bh[nj * 2][0] = r0; bh[nj * 2][1] = r1;
            bh[nj * 2 + 1][0] = r2; bh[nj * 2 + 1][1] = r3;
            ldsm_x4_t(smem_u32(wl + off), r0, r1, r2, r3);
            bl[nj * 2][0] = r0; bl[nj * 2][1] = r1;
            bl[nj * 2 + 1][0] = r2; bl[nj * 2 + 1][1] = r3;
        }
#pragma unroll
        for (int mi = 0; mi < 2; mi++)
#pragma unroll
            for (int j = 0; j < 4; j++) {
                mma_bf16(acc[mi][j], ah[mi], bh[j][0], bh[j][1]);
                mma_bf16(acc[mi][j], al[mi], bh[j][0], bh[j][1]);
                mma_bf16(acc[mi][j], ah[mi], bl[j][0], bl[j][1]);
            }
    }

    long base = (long)rt * 128;
#pragma unroll
    for (int mi = 0; mi < 2; mi++) {
#pragma unroll
        for (int j = 0; j < 4; j++) {
            int lr = wm * 32 + mi * 16 + (lane >> 2);
            int lc = wn * 32 + j * 8 + (lane & 3) * 2;
#pragma unroll
            for (int q = 0; q < 4; q++) {
                int rr = lr + (q >> 1) * 8;
                int cc = lc + (q & 1);
                float o = acc[mi][j][q] + b1s[cc];
                long gi = (base + rr) * 64 + cc;
                g_h0[gi]  = o;
                g_h0h[gi] = __float2half_rn(o);
            }
        }
    }
}

// ---------------------------------------------------------------- kernel 2: A = sum_e adj_e / (rowsum_e + 1)
// One warp per (b,n) row. Reads adj ONCE (streaming, .cs); writes fp16 A with evict_last.
__global__ void __launch_bounds__(256) k_adjA(const float* __restrict__ adj) {
    int t = threadIdx.x, lane = t & 31, wid = t >> 5;
    long R = (long)blockIdx.x * 8 + wid;        // 0 .. 32767
    long b = R >> 9;
    int  n = (int)(R & 511);
    uint64_t pol = mk_evict_last_policy();

    float4 v[4][4];
#pragma unroll
    for (int e = 0; e < 4; e++) {
        const float4* p = (const float4*)(adj + ((b * 4 + e) * 512 + n) * 512) + lane;
#pragma unroll
        for (int c = 0; c < 4; c++) v[e][c] = __ldcs(p + c * 32);
    }
    float inv[4];
#pragma unroll
    for (int e = 0; e < 4; e++) {
        float s = 0.f;
#pragma unroll
        for (int c = 0; c < 4; c++) s += v[e][c].x + v[e][c].y + v[e][c].z + v[e][c].w;
#pragma unroll
        for (int o = 16; o > 0; o >>= 1) s += __shfl_xor_sync(0xffffffffu, s, o);
        inv[e] = 1.0f / (s + 1.0f);
    }
    __half* outp = g_A + (b * 512 + n) * 512;
#pragma unroll
    for (int c = 0; c < 4; c++) {
        float a0 = v[0][c].x * inv[0] + v[1][c].x * inv[1] + v[2][c].x * inv[2] + v[3][c].x * inv[3];
        float a1 = v[0][c].y * inv[0] + v[1][c].y * inv[1] + v[2][c].y * inv[2] + v[3][c].y * inv[3];
        float a2 = v[0][c].z * inv[0] + v[1][c].z * inv[1] + v[2][c].z * inv[2] + v[3][c].z * inv[3];
        float a3 = v[0][c].w * inv[0] + v[1][c].w * inv[1] + v[2][c].w * inv[2] + v[3][c].w * inv[3];
        __half2 p0 = __floats2half2_rn(a0, a1);
        __half2 p1 = __floats2half2_rn(a2, a3);
        uint2 u;
        u.x = *reinterpret_cast<unsigned*>(&p0);
        u.y = *reinterpret_cast<unsigned*>(&p1);
        st_evl_u2(outp + c * 128 + lane * 4, u, pol);
    }
}

// ---------------------------------------------------------------- DUO kernel (fp16, 2-stage pipeline, 3 CTAs/SM):
//   Phase 1: hidden = tanh(A@h0 + h0); o0 = hidden@W2 + b2   (tile 128x64, BK=64, 8 iters)
//   per-batch ticket barrier (4 CTAs/batch; 256 CTAs at 3/SM -> all co-resident)
//   Phase 2: out = tanh(A@o0 + o0)                            (tile 128x32, BK=64, same A strip)
// 256 threads, __launch_bounds__(256,3): regs<=~84 (fp16 single-plane fits), smem 63.6KB*3=191KB<228KB.
// SMEM: AS 2*128*72*2=36864 | BS 2*64*72*2=18432 | W2 8192 | b2 128 -> 63616 B
#define D_AS   0
#define D_BS   36864
#define D_W2   55296
#define D_B2   63488
#define D_SMEM 63616

__global__ void __launch_bounds__(256, 3) k_duo(const float* __restrict__ W2,
                                                const float* __restrict__ b2,
                                                float* __restrict__ out) {
    extern __shared__ char sm[];
    __half* AS  = (__half*)(sm + D_AS);    // [2][128][72]
    __half* BS  = (__half*)(sm + D_BS);    // [2][64][72]  (phase2: [2][64][40])
    float*  W2s = (float*)(sm + D_W2);
    float*  b2s = (float*)(sm + D_B2);
    float*  Hs  = (float*)sm;              // reuse AS region between mainloops: [128][68] f32

    int t = threadIdx.x, lane = t & 31, wid = t >> 5;
    int rt = blockIdx.x, b = blockIdx.y;
    uint64_t pol = mk_evict_last_policy();
    const __half* Ag  = g_A   + ((long)b * 512 + rt * 128) * 512;
    const __half* Hgh = g_h0h + (long)b * 512 * 64;

    for (int i = t; i < 64 * 32; i += 256) W2s[i] = W2[i];
    if (t < 32) b2s[t] = b2[t];

    // A stage: 128 rows x 64 cols fp16 = 16KB = 1024 chunks, 4/thread
    auto loadA = [&](int st, int kc) {
#pragma unroll
        for (int i = 0; i < 4; i++) {
            int idx = t + i * 256;
            int r = idx >> 3, c = idx & 7;
            long g = (long)r * 512 + kc * 64 + c * 8;
            unsigned s = st * (128 * 72) + r * 72 + c * 8;
            cp_async16_pol(smem_u32(AS + s), Ag + g, pol);
        }
    };
    // B1 stage: 64 rows x 64 cols = 512 chunks, 2/thread
    auto loadB1 = [&](int st, int kc) {
#pragma unroll
        for (int i = 0; i < 2; i++) {
            int idx = t + i * 256;
            int r = idx >> 3, c = idx & 7;
            long g = (long)(kc * 64 + r) * 64 + c * 8;
            unsigned s = st * (64 * 72) + r * 72 + c * 8;
            cp_async16(smem_u32(BS + s), Hgh + g);
        }
    };

    // ================= Phase 1: 128x64 GEMM (K=512, BK=64, 8 iters)
    {
        float acc[2][4][4];
#pragma unroll
        for (int mi = 0; mi < 2; mi++)
#pragma unroll
            for (int j = 0; j < 4; j++)
#pragma unroll
                for (int q = 0; q < 4; q++) acc[mi][j][q] = 0.f;

        loadA(0, 0); loadB1(0, 0); cp_commit();

        int wm = wid & 3, wn = wid >> 2;   // 4m x 2n, warp tile 32x32

        for (int kc = 0; kc < 8; kc++) {
            int st = kc & 1;
            // uniform-commit 2-stage: commit every iter (empty at tail); wait<1> => stage kc complete
            if (kc + 1 < 8) { loadA(st ^ 1, kc + 1); loadB1(st ^ 1, kc + 1); }
            cp_commit();
            cp_wait<1>();
            __syncthreads();
            const __half* a_s = AS + st * (128 * 72);
            const __half* b_s = BS + st * (64 * 72);
#pragma unroll
            for (int ks = 0; ks < 4; ks++) {
                unsigned af[2][4];
#pragma unroll
                for (int mi = 0; mi < 2; mi++) {
                    unsigned off = (wm * 32 + mi * 16 + (lane & 15)) * 72
                                 + ks * 16 + (lane >> 4) * 8;
                    ldsm_x4(smem_u32(a_s + off), af[mi][0], af[mi][1], af[mi][2], af[mi][3]);
                }
                unsigned bf[4][2];
#pragma unroll
                for (int nj = 0; nj < 2; nj++) {
                    unsigned off = (ks * 16 + (lane & 15)) * 72
                                 + wn * 32 + nj * 16 + (lane >> 4) * 8;
                    unsigned r0, r1, r2, r3;
                    ldsm_x4_t(smem_u32(b_s + off), r0, r1, r2, r3);
                    bf[nj * 2][0] = r0; bf[nj * 2][1] = r1;
                    bf[nj * 2 + 1][0] = r2; bf[nj * 2 + 1][1] = r3;
                }
#pragma unroll
                for (int mi = 0; mi < 2; mi++)
#pragma unroll
                    for (int j = 0; j < 4; j++)
                        mma_f16(acc[mi][j], af[mi], bf[j][0], bf[j][1]);
            }
            __syncthreads();
        }

        // Epilogue 1: hidden = tanh(acc + h0_fp32) -> Hs (fp32 smem; reuses AS)
        const float* h0g = g_h0 + ((long)b * 512 + rt * 128) * 64;
#pragma unroll
        for (int mi = 0; mi < 2; mi++) {
#pragma unroll
            for (int j = 0; j < 4; j++) {
                int lr = wm * 32 + mi * 16 + (lane >> 2);
                int lc = wn * 32 + j * 8 + (lane & 3) * 2;
#pragma unroll
                for (int q = 0; q < 4; q++) {
                    int rr = lr + (q >> 1) * 8;
                    int cc = lc + (q & 1);
                    Hs[rr * 68 + cc] = tanhf(acc[mi][j][q] + h0g[rr * 64 + cc]);
                }
            }
        }
    }
    __syncthreads();

    // Epilogue 2: o0 = Hs @ W2 + b2 (fp32; hidden stays fp32 for precision)
    {
        int r = t >> 1; int dblk = (t & 1) * 16;
        float o[16];
#pragma unroll
        for (int d = 0; d < 16; d++) o[d] = b2s[dblk + d];
#pragma unroll
        for (int k = 0; k < 64; k++) {
            float hv = Hs[r * 68 + k];
#pragma unroll
            for (int d = 0; d < 16; d++) o[d] += hv * W2s[k * 32 + dblk + d];
        }
        long orow = (long)b * 512 + rt * 128 + r;
#pragma unroll
        for (int d = 0; d < 16; d++) {
            g_o0 [orow * 32 + dblk + d] = o[d];
            g_o0h[orow * 32 + dblk + d] = __float2half_rn(o[d]);
        }
    }

    // ================= Per-batch ticket barrier (4 CTAs). Monotonic counter: replay-safe.
    __threadfence();
    __syncthreads();
    if (t == 0) {
        int ticket = atomicAdd(&g_bar[b], 1);
        int target = (ticket / 4 + 1) * 4;
        while (atomicAdd(&g_bar[b], 0) < target) { }
        __threadfence();   // acquire: partner o0 stores visible
    }
    __syncthreads();

    // ================= Phase 2: out = tanh(A @ o0 + o0), tile 128x32, BK=64, same A strip (L2-hot)
    const __half* Ogh = g_o0h + (long)b * 512 * 32;

    // B2 stage: 64 rows x 32 cols = 256 chunks, 1/thread; row pitch 40
    auto loadB2 = [&](int st, int kc) {
        int r = t >> 2, c = t & 3;
        long g = (long)(kc * 64 + r) * 32 + c * 8;
        unsigned s = st * (64 * 40) + r * 40 + c * 8;
        cp_async16(smem_u32(BS + s), Ogh + g);
    };

    {
        float acc[4][4];
#pragma unroll
        for (int j = 0; j < 4; j++)
#pragma unroll
            for (int q = 0; q < 4; q++) acc[j][q] = 0.f;

        loadA(0, 0); loadB2(0, 0); cp_commit();

        for (int kc = 0; kc < 8; kc++) {
            int st = kc & 1;
            if (kc + 1 < 8) { loadA(st ^ 1, kc + 1); loadB2(st ^ 1, kc + 1); }
            cp_commit();
            cp_wait<1>();
            __syncthreads();
            const __half* a_s = AS + st * (128 * 72);
            const __half* b_s = BS + st * (64 * 40);
#pragma unroll
            for (int ks = 0; ks < 4; ks++) {
                unsigned af[4];
                {
                    unsigned off = (wid * 16 + (lane & 15)) * 72 + ks * 16 + (lane >> 4) * 8;
                    ldsm_x4(smem_u32(a_s + off), af[0], af[1], af[2], af[3]);
                }
                unsigned bf[4][2];
#pragma unroll
                for (int nj = 0; nj < 2; nj++) {
                    unsigned off = (ks * 16 + (lane & 15)) * 40 + nj * 16 + (lane >> 4) * 8;
                    unsigned r0, r1, r2, r3;
                    ldsm_x4_t(smem_u32(b_s + off), r0, r1, r2, r3);
                    bf[nj * 2][0] = r0; bf[nj * 2][1] = r1;
                    bf[nj * 2 + 1][0] = r2; bf[nj * 2 + 1][1] = r3;
                }
#pragma unroll
                for (int j = 0; j < 4; j++)
                    mma_f16(acc[j], af, bf[j][0], bf[j][1]);
            }
            __syncthreads();
        }

        // Epilogue: out = tanh(acc + o0_fp32)
        const float* o0g = g_o0 + ((long)b * 512 + rt * 128) * 32;
        float*       og  = out  + ((long)b * 512 + rt * 128) * 32;
#pragma unroll
        for (int j = 0; j < 4; j++) {
            int lr = wid * 16 + (lane >> 2);
            int lc = j * 8 + (lane & 3) * 2;
#pragma unroll
            for (int q = 0; q < 4; q++) {
                int rr = lr + (q >> 1) * 8;
                int cc = lc + (q & 1);
                og[rr * 32 + cc] = tanhf(acc[j][q] + o0g[rr * 32 + cc]);
            }
        }
    }
}

// ---------------------------------------------------------------- launcher
extern "C" void kernel_launch(void* const* d_in, const int* in_sizes, int n_in,
                              void* d_out, int out_size) {
    const float* x   = (const float*)d_in[0];
    const float* adj = (const float*)d_in[1];
    const float* W1  = (const float*)d_in[2];
    const float* b1  = (const float*)d_in[3];
    const float* W2  = (const float*)d_in[4];
    const float* b2  = (const float*)d_in[5];
    float* out = (float*)d_out;

    (void)in_sizes; (void)n_in; (void)out_size;

    cudaFuncSetAttribute(k_h0mma, cudaFuncAttributeMaxDynamicSharedMemorySize, H_SMEM);
    cudaFuncSetAttribute(k_duo,   cudaFuncAttributeMaxDynamicSharedMemorySize, D_SMEM);

    // adjA first (roofline streamer; A left L2-resident via evict_last);
    // h0 next (outputs L2-hot); duo reads A strip twice (phase2 hits L2).
    k_adjA <<<4096, 256>>>(adj);
    k_h0mma<<<256, 256, H_SMEM>>>(x, W1, b1);
    k_duo  <<<dim3(4, 64), 256, D_SMEM>>>(W2, b2, out);
}